// round 14
// baseline (speedup 1.0000x reference)
#include <cuda_runtime.h>
#include <cuda_fp16.h>
#include <stdint.h>

// Problem constants
#define F_I     512
#define F_O     32
#define F_NCH   32                 // i-chunks of 16
#define F_WROWS 16                 // rows per warp
#define F_THR   128                // 4 warps -> 64 rows per CTA

// W packed in exact mma A-fragment order:
//   g_Wf[ ((c*8 + ks)*2 + oT)*32 + lane ] = uint4{a0,a1,a2,a3}
//   A[rr][kk] = fp16( W[i = c*16+kk][o = oT*16+rr][j = ks+1] )
__device__ uint4 g_Wf[F_NCH * 8 * 2 * 32];
__device__ float g_bias[F_O];

__device__ __forceinline__ uint32_t pack2(float a, float b) {
    __half2 h = __floats2half2_rn(a, b);
    return *reinterpret_cast<uint32_t*>(&h);
}

// Fused prep: blocks 0..63 repack W fragments; block 64 computes bias.
__global__ void prep_kernel(const float* __restrict__ w) {
    if (blockIdx.x < 64) {
        int idx = blockIdx.x * 256 + threadIdx.x;      // 16384
        int l  = idx & 31;
        int oT = (idx >> 5) & 1;
        int ks = (idx >> 6) & 7;
        int c  = idx >> 9;
        int r  = l >> 2;           // A-frag row within 8 (o low)
        int cf = l & 3;            // k-quad
        int j  = ks + 1;
        int i0 = c * 16 + 2 * cf;  // a0/a1 k positions: i0, i0+1
        int i8 = i0 + 8;           // a2/a3: i8, i8+1
        int oA = oT * 16 + r;
        int oB = oA + 8;
        uint4 v;
        v.x = pack2(w[(i0 * F_O + oA) * 9 + j], w[((i0 + 1) * F_O + oA) * 9 + j]);
        v.y = pack2(w[(i0 * F_O + oB) * 9 + j], w[((i0 + 1) * F_O + oB) * 9 + j]);
        v.z = pack2(w[(i8 * F_O + oA) * 9 + j], w[((i8 + 1) * F_O + oA) * 9 + j]);
        v.w = pack2(w[(i8 * F_O + oB) * 9 + j], w[((i8 + 1) * F_O + oB) * 9 + j]);
        g_Wf[idx] = v;
    } else {
        // bias: sum of j=0 plane over i, per output o
        __shared__ float red[256];
        int t = threadIdx.x;
        int o = t & 31, g = t >> 5;
        float s = 0.0f;
#pragma unroll 8
        for (int i = g; i < F_I; i += 8) s += w[(i * F_O + o) * 9];
        red[t] = s;
        __syncthreads();
        if (t < 32) {
            float tot = 0.0f;
#pragma unroll
            for (int q = 0; q < 8; ++q) tot += red[q * 32 + t];
            g_bias[t] = tot;
        }
    }
}

__device__ __forceinline__ void mma16816(float (&d)[4], const uint4& a,
                                         uint32_t b0, uint32_t b1) {
    asm volatile(
        "mma.sync.aligned.m16n8k16.row.col.f32.f16.f16.f32 "
        "{%0,%1,%2,%3}, {%4,%5,%6,%7}, {%8,%9}, {%0,%1,%2,%3};"
        : "+f"(d[0]), "+f"(d[1]), "+f"(d[2]), "+f"(d[3])
        : "r"(a.x), "r"(a.y), "r"(a.z), "r"(a.w), "r"(b0), "r"(b1));
}
// tanh(x) = 1 - 2/(exp2(2x*log2e)+1)
__device__ __forceinline__ float ftanh(float x) {
    float p;
    asm("ex2.approx.f32 %0, %1;" : "=f"(p) : "f"(x * 2.8853900817779268f));
    float r;
    asm("rcp.approx.f32 %0, %1;" : "=f"(r) : "f"(p + 1.0f));
    return fmaf(-2.0f, r, 1.0f);
}

__global__ __launch_bounds__(F_THR, 5)
void cheby_frag_kernel(const float* __restrict__ x, float* __restrict__ out) {
    const int t    = threadIdx.x;
    const int lane = t & 31;
    const int w    = t >> 5;
    const int rowBase = blockIdx.x * (4 * F_WROWS) + w * F_WROWS;
    const int r  = lane >> 2;     // B-frag row-in-tile / A-frag o-low
    const int cf = lane & 3;

    // x pointers: tile 0 row = rowBase + r, tile 1 row = rowBase + 8 + r
    const float* xp0 = x + (size_t)(rowBase + r) * F_I + 2 * cf;
    const float* xp1 = x + (size_t)(rowBase + 8 + r) * F_I + 2 * cf;

    float acc[2][2][4];           // [oT][tile][frag]
#pragma unroll
    for (int a = 0; a < 2; ++a)
#pragma unroll
        for (int b = 0; b < 2; ++b)
#pragma unroll
            for (int q = 0; q < 4; ++q) acc[a][b][q] = 0.0f;

    // ---- prefetch chunk 0's x ----
    float2 vA0 = *reinterpret_cast<const float2*>(xp0);
    float2 vB0 = *reinterpret_cast<const float2*>(xp0 + 8);
    float2 vA1 = *reinterpret_cast<const float2*>(xp1);
    float2 vB1 = *reinterpret_cast<const float2*>(xp1 + 8);

    // ---- W fragment pipeline: w0/w1 always hold the CURRENT ks fragments ----
    const uint4* wp = g_Wf + lane;      // contiguous across (c, ks): +64 per step
    uint4 w0 = wp[0];
    uint4 w1 = wp[32];

    for (int c = 0; c < F_NCH; ++c) {
        // ---- init recurrence from prefetched x ----
        float x2[2][4], up[2][4], uc[2][4];
        {
            float xin[2][4] = {{vA0.x, vA0.y, vB0.x, vB0.y},
                               {vA1.x, vA1.y, vB1.x, vB1.y}};
#pragma unroll
            for (int tl = 0; tl < 2; ++tl)
#pragma unroll
                for (int q = 0; q < 4; ++q) {
                    float th = ftanh(xin[tl][q]);
                    x2[tl][q] = th + th;
                    up[tl][q] = 1.0f;       // U0 (folded into bias)
                    uc[tl][q] = x2[tl][q];  // U1
                }
        }

        // ---- issue next chunk's x loads; latency hides under ks loop ----
        if (c + 1 < F_NCH) {
            const int off = (c + 1) * 16;
            vA0 = *reinterpret_cast<const float2*>(xp0 + off);
            vB0 = *reinterpret_cast<const float2*>(xp0 + off + 8);
            vA1 = *reinterpret_cast<const float2*>(xp1 + off);
            vB1 = *reinterpret_cast<const float2*>(xp1 + off + 8);
        }

#pragma unroll
        for (int ks = 0; ks < 8; ++ks) {
            // preload NEXT step's W fragments (rolls across chunk boundary)
            const bool more = (c * 8 + ks + 1) < (F_NCH * 8);
            uint4 n0, n1;
            if (more) {
                n0 = wp[64];
                n1 = wp[96];
            }
            // B fragments from recurrence registers
            uint32_t b00 = pack2(uc[0][0], uc[0][1]);
            uint32_t b01 = pack2(uc[0][2], uc[0][3]);
            uint32_t b10 = pack2(uc[1][0], uc[1][1]);
            uint32_t b11 = pack2(uc[1][2], uc[1][3]);
            mma16816(acc[0][0], w0, b00, b01);
            mma16816(acc[1][0], w1, b00, b01);
            mma16816(acc[0][1], w0, b10, b11);
            mma16816(acc[1][1], w1, b10, b11);
            if (ks < 7) {
#pragma unroll
                for (int tl = 0; tl < 2; ++tl)
#pragma unroll
                    for (int q = 0; q < 4; ++q) {
                        float un = fmaf(x2[tl][q], uc[tl][q], -up[tl][q]);
                        up[tl][q] = uc[tl][q];
                        uc[tl][q] = un;
                    }
            }
            if (more) { w0 = n0; w1 = n1; }
            wp += 64;
        }
    }

    // ---- epilogue: C frag (m = o, n = batch row) + bias ----
    float b0a = g_bias[r],      b0b = g_bias[r + 8];        // oT=0
    float b1a = g_bias[16 + r], b1b = g_bias[16 + r + 8];   // oT=1
#pragma unroll
    for (int tl = 0; tl < 2; ++tl) {
        int rA = rowBase + 8 * tl + 2 * cf;
        float* pA = out + (size_t)rA * F_O;
        float* pB = pA + F_O;
        pA[r]          = acc[0][tl][0] + b0a;
        pB[r]          = acc[0][tl][1] + b0a;
        pA[r + 8]      = acc[0][tl][2] + b0b;
        pB[r + 8]      = acc[0][tl][3] + b0b;
        pA[16 + r]     = acc[1][tl][0] + b1a;
        pB[16 + r]     = acc[1][tl][1] + b1a;
        pA[16 + r + 8] = acc[1][tl][2] + b1b;
        pB[16 + r + 8] = acc[1][tl][3] + b1b;
    }
}

extern "C" void kernel_launch(void* const* d_in, const int* in_sizes, int n_in,
                              void* d_out, int out_size) {
    const float* x  = (const float*)d_in[0];     // [65536, 512] f32
    const float* wc = (const float*)d_in[1];     // [512, 32, 9] f32
    float* out = (float*)d_out;                  // [65536, 32] f32

    int Brows = in_sizes[0] / F_I;               // 65536

    prep_kernel<<<65, 256>>>(wc);                // repack (blocks 0-63) + bias (block 64)

    cheby_frag_kernel<<<Brows / 64, F_THR>>>(x, out);
}

// round 15
// speedup vs baseline: 1.7521x; 1.7521x over previous
#include <cuda_runtime.h>
#include <cuda_fp16.h>
#include <stdint.h>

// Problem constants
#define F_I     512
#define F_O     32
#define F_NCH   32                 // i-chunks of 16
#define F_WROWS 16                 // rows per warp
#define F_THR   128                // 4 warps -> 64 rows per CTA

// W packed in exact mma A-fragment order (+64 pad entries so the rolling
// pipeline can over-read one step past the end, branch-free):
//   g_Wf[ ((c*8 + ks)*2 + oT)*32 + lane ] = uint4{a0,a1,a2,a3}
//   A[rr][kk] = fp16( W[i = c*16+kk][o = oT*16+rr][j = ks+1] )
__device__ uint4 g_Wf[F_NCH * 8 * 2 * 32 + 64];
__device__ float g_bias[F_O];

__device__ __forceinline__ uint32_t pack2(float a, float b) {
    __half2 h = __floats2half2_rn(a, b);
    return *reinterpret_cast<uint32_t*>(&h);
}

// Fused prep: blocks 0..63 repack W fragments; block 64 computes bias.
__global__ void prep_kernel(const float* __restrict__ w) {
    if (blockIdx.x < 64) {
        int idx = blockIdx.x * 256 + threadIdx.x;      // 16384
        int l  = idx & 31;
        int oT = (idx >> 5) & 1;
        int ks = (idx >> 6) & 7;
        int c  = idx >> 9;
        int r  = l >> 2;           // A-frag row within 8 (o low)
        int cf = l & 3;            // k-quad
        int j  = ks + 1;
        int i0 = c * 16 + 2 * cf;  // a0/a1 k positions: i0, i0+1
        int i8 = i0 + 8;           // a2/a3: i8, i8+1
        int oA = oT * 16 + r;
        int oB = oA + 8;
        uint4 v;
        v.x = pack2(w[(i0 * F_O + oA) * 9 + j], w[((i0 + 1) * F_O + oA) * 9 + j]);
        v.y = pack2(w[(i0 * F_O + oB) * 9 + j], w[((i0 + 1) * F_O + oB) * 9 + j]);
        v.z = pack2(w[(i8 * F_O + oA) * 9 + j], w[((i8 + 1) * F_O + oA) * 9 + j]);
        v.w = pack2(w[(i8 * F_O + oB) * 9 + j], w[((i8 + 1) * F_O + oB) * 9 + j]);
        g_Wf[idx] = v;
    } else {
        // bias: sum of j=0 plane over i, per output o (+ zero the pad entries)
        __shared__ float red[256];
        int t = threadIdx.x;
        if (t < 64) g_Wf[F_NCH * 8 * 2 * 32 + t] = make_uint4(0, 0, 0, 0);
        int o = t & 31, g = t >> 5;
        float s = 0.0f;
#pragma unroll 8
        for (int i = g; i < F_I; i += 8) s += w[(i * F_O + o) * 9];
        red[t] = s;
        __syncthreads();
        if (t < 32) {
            float tot = 0.0f;
#pragma unroll
            for (int q = 0; q < 8; ++q) tot += red[q * 32 + t];
            g_bias[t] = tot;
        }
    }
}

__device__ __forceinline__ void mma16816(float (&d)[4], const uint4& a,
                                         uint32_t b0, uint32_t b1) {
    asm volatile(
        "mma.sync.aligned.m16n8k16.row.col.f32.f16.f16.f32 "
        "{%0,%1,%2,%3}, {%4,%5,%6,%7}, {%8,%9}, {%0,%1,%2,%3};"
        : "+f"(d[0]), "+f"(d[1]), "+f"(d[2]), "+f"(d[3])
        : "r"(a.x), "r"(a.y), "r"(a.z), "r"(a.w), "r"(b0), "r"(b1));
}
// tanh(x) = 1 - 2/(exp2(2x*log2e)+1)
__device__ __forceinline__ float ftanh(float x) {
    float p;
    asm("ex2.approx.f32 %0, %1;" : "=f"(p) : "f"(x * 2.8853900817779268f));
    float r;
    asm("rcp.approx.f32 %0, %1;" : "=f"(r) : "f"(p + 1.0f));
    return fmaf(-2.0f, r, 1.0f);
}

__global__ __launch_bounds__(F_THR, 5)
void cheby_frag_kernel(const float* __restrict__ x, float* __restrict__ out) {
    const int t    = threadIdx.x;
    const int lane = t & 31;
    const int w    = t >> 5;
    const int rowBase = blockIdx.x * (4 * F_WROWS) + w * F_WROWS;
    const int r  = lane >> 2;     // B-frag row-in-tile / A-frag o-low
    const int cf = lane & 3;

    // x pointers: tile 0 row = rowBase + r, tile 1 row = rowBase + 8 + r
    const float* xp0 = x + (size_t)(rowBase + r) * F_I + 2 * cf;
    const float* xp1 = x + (size_t)(rowBase + 8 + r) * F_I + 2 * cf;

    float acc[2][2][4];           // [oT][tile][frag]
#pragma unroll
    for (int a = 0; a < 2; ++a)
#pragma unroll
        for (int b = 0; b < 2; ++b)
#pragma unroll
            for (int q = 0; q < 4; ++q) acc[a][b][q] = 0.0f;

    // ---- prefetch chunk 0's x ----
    float2 vA0 = *reinterpret_cast<const float2*>(xp0);
    float2 vB0 = *reinterpret_cast<const float2*>(xp0 + 8);
    float2 vA1 = *reinterpret_cast<const float2*>(xp1);
    float2 vB1 = *reinterpret_cast<const float2*>(xp1 + 8);

    // ---- W rolling pipeline: w0/w1 = CURRENT step fragments, branch-free ----
    const uint4* wp = g_Wf + lane;      // contiguous across (c, ks): +64 per step
    uint4 w0 = wp[0];
    uint4 w1 = wp[32];

    for (int c = 0; c < F_NCH; ++c) {
        // ---- init recurrence from prefetched x ----
        float x2[2][4], up[2][4], uc[2][4];
        {
            float xin[2][4] = {{vA0.x, vA0.y, vB0.x, vB0.y},
                               {vA1.x, vA1.y, vB1.x, vB1.y}};
#pragma unroll
            for (int tl = 0; tl < 2; ++tl)
#pragma unroll
                for (int q = 0; q < 4; ++q) {
                    float th = ftanh(xin[tl][q]);
                    x2[tl][q] = th + th;
                    up[tl][q] = 1.0f;       // U0 (folded into bias)
                    uc[tl][q] = x2[tl][q];  // U1
                }
        }

        // ---- issue next chunk's x loads; latency hides under ks loop ----
        if (c + 1 < F_NCH) {
            const int off = (c + 1) * 16;
            vA0 = *reinterpret_cast<const float2*>(xp0 + off);
            vB0 = *reinterpret_cast<const float2*>(xp0 + off + 8);
            vA1 = *reinterpret_cast<const float2*>(xp1 + off);
            vB1 = *reinterpret_cast<const float2*>(xp1 + off + 8);
        }

#pragma unroll
        for (int ks = 0; ks < 8; ++ks) {
            // preload NEXT step's W fragments — unconditional (pad makes it legal)
            uint4 n0 = wp[64];
            uint4 n1 = wp[96];
            // pack B fragments from current recurrence state
            uint32_t b00 = pack2(uc[0][0], uc[0][1]);
            uint32_t b01 = pack2(uc[0][2], uc[0][3]);
            uint32_t b10 = pack2(uc[1][0], uc[1][1]);
            uint32_t b11 = pack2(uc[1][2], uc[1][3]);
            // advance recurrence BEFORE MMAs: FFMAs dual-issue under HMMA
#pragma unroll
            for (int tl = 0; tl < 2; ++tl)
#pragma unroll
                for (int q = 0; q < 4; ++q) {
                    float un = fmaf(x2[tl][q], uc[tl][q], -up[tl][q]);
                    up[tl][q] = uc[tl][q];
                    uc[tl][q] = un;
                }
            mma16816(acc[0][0], w0, b00, b01);
            mma16816(acc[1][0], w1, b00, b01);
            mma16816(acc[0][1], w0, b10, b11);
            mma16816(acc[1][1], w1, b10, b11);
            w0 = n0;
            w1 = n1;
            wp += 64;
        }
    }

    // ---- epilogue: C frag (m = o, n = batch row) + bias ----
    float b0a = g_bias[r],      b0b = g_bias[r + 8];        // oT=0
    float b1a = g_bias[16 + r], b1b = g_bias[16 + r + 8];   // oT=1
#pragma unroll
    for (int tl = 0; tl < 2; ++tl) {
        int rA = rowBase + 8 * tl + 2 * cf;
        float* pA = out + (size_t)rA * F_O;
        float* pB = pA + F_O;
        pA[r]          = acc[0][tl][0] + b0a;
        pB[r]          = acc[0][tl][1] + b0a;
        pA[r + 8]      = acc[0][tl][2] + b0b;
        pB[r + 8]      = acc[0][tl][3] + b0b;
        pA[16 + r]     = acc[1][tl][0] + b1a;
        pB[16 + r]     = acc[1][tl][1] + b1a;
        pA[16 + r + 8] = acc[1][tl][2] + b1b;
        pB[16 + r + 8] = acc[1][tl][3] + b1b;
    }
}

extern "C" void kernel_launch(void* const* d_in, const int* in_sizes, int n_in,
                              void* d_out, int out_size) {
    const float* x  = (const float*)d_in[0];     // [65536, 512] f32
    const float* wc = (const float*)d_in[1];     // [512, 32, 9] f32
    float* out = (float*)d_out;                  // [65536, 32] f32

    int Brows = in_sizes[0] / F_I;               // 65536

    prep_kernel<<<65, 256>>>(wc);                // repack (blocks 0-63) + bias (block 64)

    cheby_frag_kernel<<<Brows / 64, F_THR>>>(x, out);
}

// round 16
// speedup vs baseline: 2.0039x; 1.1437x over previous
#include <cuda_runtime.h>
#include <cuda_fp16.h>
#include <stdint.h>

// Problem constants
#define F_I     512
#define F_O     32
#define F_NCH   32                 // i-chunks of 16
#define F_WROWS 16                 // rows per warp
#define F_THR   128                // 4 warps -> 64 rows per CTA

// W packed in exact mma A-fragment order:
//   g_Wf[ ((c*8 + ks)*2 + oT)*32 + lane ] = uint4{a0,a1,a2,a3}
//   A[rr][kk] = fp16( W[i = c*16+kk][o = oT*16+rr][j = ks+1] )
__device__ uint4 g_Wf[F_NCH * 8 * 2 * 32];
__device__ float g_bias[F_O];

__device__ __forceinline__ uint32_t pack2(float a, float b) {
    __half2 h = __floats2half2_rn(a, b);
    return *reinterpret_cast<uint32_t*>(&h);
}

// Fused prep: blocks 0..63 repack W fragments; block 64 computes bias.
__global__ void prep_kernel(const float* __restrict__ w) {
    if (blockIdx.x < 64) {
        int idx = blockIdx.x * 256 + threadIdx.x;      // 16384
        int l  = idx & 31;
        int oT = (idx >> 5) & 1;
        int ks = (idx >> 6) & 7;
        int c  = idx >> 9;
        int r  = l >> 2;           // A-frag row within 8 (o low)
        int cf = l & 3;            // k-quad
        int j  = ks + 1;
        int i0 = c * 16 + 2 * cf;  // a0/a1 k positions: i0, i0+1
        int i8 = i0 + 8;           // a2/a3: i8, i8+1
        int oA = oT * 16 + r;
        int oB = oA + 8;
        uint4 v;
        v.x = pack2(w[(i0 * F_O + oA) * 9 + j], w[((i0 + 1) * F_O + oA) * 9 + j]);
        v.y = pack2(w[(i0 * F_O + oB) * 9 + j], w[((i0 + 1) * F_O + oB) * 9 + j]);
        v.z = pack2(w[(i8 * F_O + oA) * 9 + j], w[((i8 + 1) * F_O + oA) * 9 + j]);
        v.w = pack2(w[(i8 * F_O + oB) * 9 + j], w[((i8 + 1) * F_O + oB) * 9 + j]);
        g_Wf[idx] = v;
    } else {
        // bias: sum of j=0 plane over i, per output o
        __shared__ float red[256];
        int t = threadIdx.x;
        int o = t & 31, g = t >> 5;
        float s = 0.0f;
#pragma unroll 8
        for (int i = g; i < F_I; i += 8) s += w[(i * F_O + o) * 9];
        red[t] = s;
        __syncthreads();
        if (t < 32) {
            float tot = 0.0f;
#pragma unroll
            for (int q = 0; q < 8; ++q) tot += red[q * 32 + t];
            g_bias[t] = tot;
        }
    }
}

__device__ __forceinline__ void mma16816(float (&d)[4], const uint32_t (&a)[4],
                                         uint32_t b0, uint32_t b1) {
    asm volatile(
        "mma.sync.aligned.m16n8k16.row.col.f32.f16.f16.f32 "
        "{%0,%1,%2,%3}, {%4,%5,%6,%7}, {%8,%9}, {%0,%1,%2,%3};"
        : "+f"(d[0]), "+f"(d[1]), "+f"(d[2]), "+f"(d[3])
        : "r"(a[0]), "r"(a[1]), "r"(a[2]), "r"(a[3]), "r"(b0), "r"(b1));
}
// tanh(x) = 1 - 2/(exp2(2x*log2e)+1)
__device__ __forceinline__ float ftanh(float x) {
    float p;
    asm("ex2.approx.f32 %0, %1;" : "=f"(p) : "f"(x * 2.8853900817779268f));
    float r;
    asm("rcp.approx.f32 %0, %1;" : "=f"(r) : "f"(p + 1.0f));
    return fmaf(-2.0f, r, 1.0f);
}

__global__ __launch_bounds__(F_THR, 4)
void cheby_frag_kernel(const float* __restrict__ x, float* __restrict__ out) {
    const int t    = threadIdx.x;
    const int lane = t & 31;
    const int w    = t >> 5;
    const int rowBase = blockIdx.x * (4 * F_WROWS) + w * F_WROWS;
    const int r  = lane >> 2;     // B-frag row-in-tile / A-frag o-low
    const int cf = lane & 3;

    // x pointers: tile 0 row = rowBase + r, tile 1 row = rowBase + 8 + r
    const float* xp0 = x + (size_t)(rowBase + r) * F_I + 2 * cf;
    const float* xp1 = x + (size_t)(rowBase + 8 + r) * F_I + 2 * cf;

    // split accumulators: [ks-parity][oT][tile][frag]  -> 8 independent HMMA chains
    float acc[2][2][2][4];
#pragma unroll
    for (int p = 0; p < 2; ++p)
#pragma unroll
        for (int a = 0; a < 2; ++a)
#pragma unroll
            for (int b = 0; b < 2; ++b)
#pragma unroll
                for (int q = 0; q < 4; ++q) acc[p][a][b][q] = 0.0f;

    // ---- prefetch chunk 0's x ----
    float2 vA0 = *reinterpret_cast<const float2*>(xp0);
    float2 vB0 = *reinterpret_cast<const float2*>(xp0 + 8);
    float2 vA1 = *reinterpret_cast<const float2*>(xp1);
    float2 vB1 = *reinterpret_cast<const float2*>(xp1 + 8);

    const uint4* wp0 = g_Wf + lane;

    for (int c = 0; c < F_NCH; ++c) {
        // ---- init recurrence from prefetched x ----
        float x2[2][4], up[2][4], uc[2][4];
        {
            float xin[2][4] = {{vA0.x, vA0.y, vB0.x, vB0.y},
                               {vA1.x, vA1.y, vB1.x, vB1.y}};
#pragma unroll
            for (int tl = 0; tl < 2; ++tl)
#pragma unroll
                for (int q = 0; q < 4; ++q) {
                    float th = ftanh(xin[tl][q]);
                    x2[tl][q] = th + th;
                    up[tl][q] = 1.0f;       // U0 (folded into bias)
                    uc[tl][q] = x2[tl][q];  // U1
                }
        }

        // ---- issue next chunk's x loads; latency hides under ks loop ----
        if (c + 1 < F_NCH) {
            const int off = (c + 1) * 16;
            vA0 = *reinterpret_cast<const float2*>(xp0 + off);
            vB0 = *reinterpret_cast<const float2*>(xp0 + off + 8);
            vA1 = *reinterpret_cast<const float2*>(xp1 + off);
            vB1 = *reinterpret_cast<const float2*>(xp1 + off + 8);
        }

        const uint4* wp = wp0 + c * (8 * 2 * 32);
#pragma unroll
        for (int ks = 0; ks < 8; ++ks) {
            const int par = ks & 1;            // compile-time in unrolled loop
            uint4 w0 = wp[0];
            uint4 w1 = wp[32];
            wp += 64;
            uint32_t a0[4] = {w0.x, w0.y, w0.z, w0.w};
            uint32_t a1[4] = {w1.x, w1.y, w1.z, w1.w};
#pragma unroll
            for (int tl = 0; tl < 2; ++tl) {
                uint32_t b0 = pack2(uc[tl][0], uc[tl][1]);
                uint32_t b1 = pack2(uc[tl][2], uc[tl][3]);
                mma16816(acc[par][0][tl], a0, b0, b1);
                mma16816(acc[par][1][tl], a1, b0, b1);
            }
            if (ks < 7) {
#pragma unroll
                for (int tl = 0; tl < 2; ++tl)
#pragma unroll
                    for (int q = 0; q < 4; ++q) {
                        float un = fmaf(x2[tl][q], uc[tl][q], -up[tl][q]);
                        up[tl][q] = uc[tl][q];
                        uc[tl][q] = un;
                    }
            }
        }
    }

    // ---- epilogue: merge parity accumulators, add bias, store ----
    float b0a = g_bias[r],      b0b = g_bias[r + 8];        // oT=0
    float b1a = g_bias[16 + r], b1b = g_bias[16 + r + 8];   // oT=1
#pragma unroll
    for (int tl = 0; tl < 2; ++tl) {
        int rA = rowBase + 8 * tl + 2 * cf;
        float* pA = out + (size_t)rA * F_O;
        float* pB = pA + F_O;
        pA[r]          = acc[0][0][tl][0] + acc[1][0][tl][0] + b0a;
        pB[r]          = acc[0][0][tl][1] + acc[1][0][tl][1] + b0a;
        pA[r + 8]      = acc[0][0][tl][2] + acc[1][0][tl][2] + b0b;
        pB[r + 8]      = acc[0][0][tl][3] + acc[1][0][tl][3] + b0b;
        pA[16 + r]     = acc[0][1][tl][0] + acc[1][1][tl][0] + b1a;
        pB[16 + r]     = acc[0][1][tl][1] + acc[1][1][tl][1] + b1a;
        pA[16 + r + 8] = acc[0][1][tl][2] + acc[1][1][tl][2] + b1b;
        pB[16 + r + 8] = acc[0][1][tl][3] + acc[1][1][tl][3] + b1b;
    }
}

extern "C" void kernel_launch(void* const* d_in, const int* in_sizes, int n_in,
                              void* d_out, int out_size) {
    const float* x  = (const float*)d_in[0];     // [65536, 512] f32
    const float* wc = (const float*)d_in[1];     // [512, 32, 9] f32
    float* out = (float*)d_out;                  // [65536, 32] f32

    int Brows = in_sizes[0] / F_I;               // 65536

    prep_kernel<<<65, 256>>>(wc);                // repack (blocks 0-63) + bias (block 64)

    cheby_frag_kernel<<<Brows / 64, F_THR>>>(x, out);
}